// round 12
// baseline (speedup 1.0000x reference)
#include <cuda_runtime.h>
#include <math.h>

#define N      4096
#define D      128
#define NW     128          // 4096 bits / 32
#define MLP_R  16           // rows per MLP block
#define XSTRIDE 36          // dup-x smem row stride (floats)
#define CAP    192          // per-row unique-neighbor list capacity
#define GS     33           // padded stride for a 32-float group in smem
#define MEGA_B 512          // mega kernel blocks (all resident: 148*4=592)
#define INV232 2.3283064365386963e-10f   // 2^-32

// ---------------- scratch (device globals) ----------------------------------
__device__ unsigned       g_A  [N * NW];
__device__ unsigned       g_A2 [N * NW];
__device__ unsigned short g_nbr[N * CAP];   // unique neighbor lists
__device__ int            g_cnt[N];
__device__ float          g_Wt [3 * D * D]; // pre-transposed weights, k-major
__device__ float          g_a0[N];
__device__ float          g_av2[N];
__device__ long long      g_stepq[N];
__device__ float          g_step[N];
__device__ int            g_is64;
__device__ unsigned       g_sync1, g_sync2; // grid barriers (reset by prep)

#define FMA2(acc, w, x) asm("fma.rn.f32x2 %0, %1, %2, %0;" : "+l"(acc) : "l"(w), "l"(x))
union U64F2 { unsigned long long u; float2 f; };

// ---------------- grid-wide barrier (all blocks provably resident) ----------
__device__ __forceinline__ void grid_barrier(unsigned* cnt, unsigned nblocks) {
    __syncthreads();
    if (threadIdx.x == 0) {
        __threadfence();                      // release (cumulative)
        atomicAdd(cnt, 1u);
        unsigned v;
        do {
            asm volatile("ld.acquire.gpu.global.u32 %0, [%1];"
                         : "=r"(v) : "l"(cnt));
        } while (v < nblocks);
    }
    __syncthreads();
}

// ---------------- prep: zero A/cnt/stepq/syncs + transpose W + detect -------
__global__ void prep_kernel(const float* __restrict__ W0,
                            const float* __restrict__ W1,
                            const float* __restrict__ W2,
                            const void* __restrict__ ei) {
    if (blockIdx.x == gridDim.x - 1) {
        __shared__ int bad;
        if (threadIdx.x == 0) bad = 0;
        __syncthreads();
        const long long* p = (const long long*)ei;
        for (int i = threadIdx.x; i < 2048; i += blockDim.x) {
            long long v = p[i];
            if (v < 0 || v >= N) bad = 1;
        }
        __syncthreads();
        if (threadIdx.x == 0) g_is64 = bad ? 0 : 1;
        return;
    }
    int idx = blockIdx.x * 256 + threadIdx.x;
    if (idx == 0) { g_sync1 = 0u; g_sync2 = 0u; }
    if (idx < N * NW) {
        g_A[idx] = 0u;
        if (idx < N) { g_stepq[idx] = 0ll; g_cnt[idx] = 0; }
    } else {
        int t = idx - N * NW;
        int m  = t >> 14;
        int tp = t & 16383;                  // tp = k*128 + c
        int c  = tp & 127;
        int k  = tp >> 7;
        const float* Ws = (m == 0) ? W0 : (m == 1 ? W1 : W2);
        g_Wt[m * 16384 + tp] = Ws[c * 128 + k];
    }
}

// ---------------- fused MLP: 3 x (GEMM+ReLU) + final dot, one kernel --------
__global__ __launch_bounds__(128, 4)
void mlp_kernel(const float* __restrict__ coeffs,
                const float* __restrict__ b0,
                const float* __restrict__ W3,
                const float* __restrict__ b3) {
    __shared__ float xa[128 * XSTRIDE];
    __shared__ float xb[128 * XSTRIDE];

    const int tid = threadIdx.x;
    const int r0  = blockIdx.x * MLP_R;
    const int rg  = tid >> 4;     // 8 row-groups of 2 rows
    const int cg  = tid & 15;     // 16 col-groups

    #pragma unroll
    for (int it = 0; it < 4; it++) {
        int idx = it * 128 + tid;
        int r  = idx >> 5;
        int kq = idx & 31;
        float4 v = *(const float4*)&coeffs[(r0 + r) * 128 + kq * 4];
        float vv[4] = {v.x, v.y, v.z, v.w};
        #pragma unroll
        for (int q = 0; q < 4; q++)
            *(float2*)&xa[(kq * 4 + q) * XSTRIDE + 2 * r] = make_float2(vv[q], vv[q]);
    }
    __syncthreads();

    float* Xin  = xa;
    float* Xout = xb;

    #pragma unroll
    for (int layer = 0; layer < 3; layer++) {
        const float* Wl = g_Wt + layer * 16384;

        unsigned long long a0p[4], a1p[4];
        #pragma unroll
        for (int j = 0; j < 4; j++) { a0p[j] = 0ull; a1p[j] = 0ull; }

        #pragma unroll 8
        for (int k = 0; k < 128; k++) {
            ulonglong2 xx = *(const ulonglong2*)&Xin[k * XSTRIDE + rg * 4];
            const float* wrow = Wl + k * 128 + cg * 2;
            unsigned long long w0 = *(const unsigned long long*)(wrow);
            unsigned long long w1 = *(const unsigned long long*)(wrow + 32);
            unsigned long long w2 = *(const unsigned long long*)(wrow + 64);
            unsigned long long w3 = *(const unsigned long long*)(wrow + 96);
            FMA2(a0p[0], w0, xx.x); FMA2(a1p[0], w0, xx.y);
            FMA2(a0p[1], w1, xx.x); FMA2(a1p[1], w1, xx.y);
            FMA2(a0p[2], w2, xx.x); FMA2(a1p[2], w2, xx.y);
            FMA2(a0p[3], w3, xx.x); FMA2(a1p[3], w3, xx.y);
        }

        float o0[8], o1[8];
        #pragma unroll
        for (int j = 0; j < 4; j++) {
            U64F2 u0, u1; u0.u = a0p[j]; u1.u = a1p[j];
            o0[2 * j] = u0.f.x; o0[2 * j + 1] = u0.f.y;
            o1[2 * j] = u1.f.x; o1[2 * j + 1] = u1.f.y;
        }
        if (layer == 0) {
            #pragma unroll
            for (int j = 0; j < 4; j++) {
                float2 bb = *(const float2*)&b0[32 * j + cg * 2];
                o0[2 * j] += bb.x; o0[2 * j + 1] += bb.y;
                o1[2 * j] += bb.x; o1[2 * j + 1] += bb.y;
            }
        }
        #pragma unroll
        for (int j = 0; j < 8; j++) {
            o0[j] = fmaxf(o0[j], 0.f);
            o1[j] = fmaxf(o1[j], 0.f);
        }

        if (layer < 2) {
            #pragma unroll
            for (int j = 0; j < 4; j++) {
                int k0 = cg * 2 + 32 * j;
                *(float2*)&Xout[(k0    ) * XSTRIDE + 4 * rg    ] = make_float2(o0[2*j],   o0[2*j]);
                *(float2*)&Xout[(k0 + 1) * XSTRIDE + 4 * rg    ] = make_float2(o0[2*j+1], o0[2*j+1]);
                *(float2*)&Xout[(k0    ) * XSTRIDE + 4 * rg + 2] = make_float2(o1[2*j],   o1[2*j]);
                *(float2*)&Xout[(k0 + 1) * XSTRIDE + 4 * rg + 2] = make_float2(o1[2*j+1], o1[2*j+1]);
            }
            __syncthreads();
            float* tmp = Xin; Xin = Xout; Xout = tmp;
        } else {
            float p0 = 0.f, p1 = 0.f;
            #pragma unroll
            for (int j = 0; j < 4; j++) {
                float2 w3v = *(const float2*)&W3[32 * j + cg * 2];
                p0 = fmaf(o0[2*j], w3v.x, fmaf(o0[2*j+1], w3v.y, p0));
                p1 = fmaf(o1[2*j], w3v.x, fmaf(o1[2*j+1], w3v.y, p1));
            }
            #pragma unroll
            for (int off = 8; off; off >>= 1) {
                p0 += __shfl_down_sync(0xffffffffu, p0, off, 16);
                p1 += __shfl_down_sync(0xffffffffu, p1, off, 16);
            }
            if (cg == 0) {
                float bb = b3[0];
                g_a0[r0 + rg * 2]     = p0 + bb;
                g_a0[r0 + rg * 2 + 1] = p1 + bb;
            }
        }
    }
}

// ---------------- hop body (shared by both phases) ----------------------------
__device__ __forceinline__ void hop_body(int phase, float* __restrict__ out_final,
                                         float* vsh, float* seg, float* part,
                                         int blk) {
    const unsigned* M = phase ? g_A2 : g_A;

    const int tid  = threadIdx.x;
    const int wid  = tid >> 5;
    const int lane = tid & 31;
    const int r    = wid >> 1;          // row within block (0..7)
    const int h    = wid & 1;           // column half (0..1)
    const int i    = blk * 8 + r;

    // ---- 1. OR over neighbor rows via unique neighbor list ------------------
    const int woff = h * 64 + 2 * lane;              // this lane's word pair
    const int cnt  = g_cnt[i];
    unsigned ax = 0u, ay = 0u;

    if (cnt <= CAP) {
        const unsigned short* nb = g_nbr + i * CAP;
        int j = 0;
        for (; j + 8 <= cnt; j += 8) {
            uint4 nn = *(const uint4*)&nb[j];        // 8 ushorts, uniform
            int n0 = nn.x & 0xffff, n1 = nn.x >> 16;
            int n2 = nn.y & 0xffff, n3 = nn.y >> 16;
            int n4 = nn.z & 0xffff, n5 = nn.z >> 16;
            int n6 = nn.w & 0xffff, n7 = nn.w >> 16;
            uint2 q0 = __ldg((const uint2*)&M[n0 * NW + woff]);
            uint2 q1 = __ldg((const uint2*)&M[n1 * NW + woff]);
            uint2 q2 = __ldg((const uint2*)&M[n2 * NW + woff]);
            uint2 q3 = __ldg((const uint2*)&M[n3 * NW + woff]);
            uint2 q4 = __ldg((const uint2*)&M[n4 * NW + woff]);
            uint2 q5 = __ldg((const uint2*)&M[n5 * NW + woff]);
            uint2 q6 = __ldg((const uint2*)&M[n6 * NW + woff]);
            uint2 q7 = __ldg((const uint2*)&M[n7 * NW + woff]);
            ax |= ((q0.x | q1.x) | (q2.x | q3.x)) | ((q4.x | q5.x) | (q6.x | q7.x));
            ay |= ((q0.y | q1.y) | (q2.y | q3.y)) | ((q4.y | q5.y) | (q6.y | q7.y));
        }
        for (; j < cnt; j++) {
            int n = nb[j];
            uint2 q = __ldg((const uint2*)&M[n * NW + woff]);
            ax |= q.x; ay |= q.y;
        }
    } else {
        // fallback: bit-walk over the adjacency row (pathological degrees)
        const uint4* Arow = (const uint4*)&g_A[i * NW];
        for (int c = 0; c < 32; c++) {
            uint4 mw = __ldg(&Arow[c]);
            int jb = c * 128;
            unsigned m;
            m = mw.x; while (m) { int b = __ffs((int)m) - 1; m &= m - 1;
                uint2 q = *(const uint2*)&M[(jb + b) * NW + woff]; ax |= q.x; ay |= q.y; }
            m = mw.y; while (m) { int b = __ffs((int)m) - 1; m &= m - 1;
                uint2 q = *(const uint2*)&M[(jb + 32 + b) * NW + woff]; ax |= q.x; ay |= q.y; }
            m = mw.z; while (m) { int b = __ffs((int)m) - 1; m &= m - 1;
                uint2 q = *(const uint2*)&M[(jb + 64 + b) * NW + woff]; ax |= q.x; ay |= q.y; }
            m = mw.w; while (m) { int b = __ffs((int)m) - 1; m &= m - 1;
                uint2 q = *(const uint2*)&M[(jb + 96 + b) * NW + woff]; ax |= q.x; ay |= q.y; }
        }
    }

    if (!phase) *(uint2*)&g_A2[i * NW + woff] = make_uint2(ax, ay);

    // ---- 2. load angle vector, store to padded smem + per-group sums -------
    {
        float vv[8];
        if (phase) {
            float4 u0 = *(const float4*)&g_av2[tid * 8];
            float4 u1 = *(const float4*)&g_av2[tid * 8 + 4];
            vv[0]=u0.x; vv[1]=u0.y; vv[2]=u0.z; vv[3]=u0.w;
            vv[4]=u1.x; vv[5]=u1.y; vv[6]=u1.z; vv[7]=u1.w;
        } else {
            float4 u0 = *(const float4*)&g_a0[tid * 8];
            float4 u1 = *(const float4*)&g_a0[tid * 8 + 4];
            const longlong2* sq = (const longlong2*)g_stepq + tid * 4;
            longlong2 q0 = sq[0], q1 = sq[1], q2 = sq[2], q3 = sq[3];
            vv[0] = u0.x + __ll2float_rn(q0.x) * INV232;
            vv[1] = u0.y + __ll2float_rn(q0.y) * INV232;
            vv[2] = u0.z + __ll2float_rn(q1.x) * INV232;
            vv[3] = u0.w + __ll2float_rn(q1.y) * INV232;
            vv[4] = u1.x + __ll2float_rn(q2.x) * INV232;
            vv[5] = u1.y + __ll2float_rn(q2.y) * INV232;
            vv[6] = u1.z + __ll2float_rn(q3.x) * INV232;
            vv[7] = u1.w + __ll2float_rn(q3.y) * INV232;
        }
        const int g  = tid >> 2;            // 32-float group (one per 4 threads)
        const int o0 = (tid & 3) * 8;       // offset within group
        float s = 0.f;
        #pragma unroll
        for (int q = 0; q < 8; q++) {
            vsh[g * GS + o0 + q] = vv[q];
            s += vv[q];
        }
        s += __shfl_down_sync(0xffffffffu, s, 2, 4);
        s += __shfl_down_sync(0xffffffffu, s, 1, 4);
        if ((tid & 3) == 0) seg[g] = s;
    }
    __syncthreads();

    // ---- 3. gated sum over this lane's two 32-float groups ------------------
    const float* base0 = vsh + woff * GS;          // group woff
    const float* base1 = vsh + (woff + 1) * GS;    // group woff+1
    int pc = __popc(ax) + __popc(ay);
    float sv;
    if (pc > 32) {
        sv = seg[woff] + seg[woff + 1];
        unsigned m;
        m = ~ax; while (m) { int b = __ffs((int)m) - 1; m &= m - 1; sv -= base0[b]; }
        m = ~ay; while (m) { int b = __ffs((int)m) - 1; m &= m - 1; sv -= base1[b]; }
    } else {
        sv = 0.f;
        unsigned m;
        m = ax; while (m) { int b = __ffs((int)m) - 1; m &= m - 1; sv += base0[b]; }
        m = ay; while (m) { int b = __ffs((int)m) - 1; m &= m - 1; sv += base1[b]; }
    }
    #pragma unroll
    for (int o = 16; o; o >>= 1) sv += __shfl_down_sync(0xffffffffu, sv, o);
    if (lane == 0) part[wid] = sv;
    __syncthreads();

    // ---- 4. combine halves + epilogue (threads 0..7 handle rows 0..7) ------
    if (tid < 8) {
        const int ii = blk * 8 + tid;
        float vi = vsh[(ii >> 5) * GS + (ii & 31)];
        float tot = part[2 * tid] + part[2 * tid + 1];
        if (!phase) {
            float s1 = __ll2float_rn(g_stepq[ii]) * INV232;
            float ns = s1 + 1.0986122886681098f * tot;            // ln 3
            g_step[ii] = ns;
            g_av2[ii]  = vi + ns;                                  // a1 + step
        } else {
            out_final[ii] = vi + g_step[ii] + 1.3862943611198906f * tot; // ln 4
        }
    }
}

// ---------------- mega: edge scatter + grid barrier + hop0 + barrier + hop1 --
__global__ __launch_bounds__(512, 4)
void mega_kernel(const void* __restrict__ ei, int ne, float* __restrict__ out) {
    __shared__ float vsh[128 * GS];
    __shared__ float seg[128];
    __shared__ float part[16];

    // ---- edge part: bitset + unique neighbor list + hop-1 scatter ----------
    const int stride = gridDim.x * blockDim.x;
    for (int e = blockIdx.x * blockDim.x + threadIdx.x; e < ne; e += stride) {
        int row, col;
        if (g_is64) {
            const long long* p = (const long long*)ei;
            row = (int)p[e];
            col = (int)p[ne + e];
        } else {
            const int* p = (const int*)ei;
            row = p[e];
            col = p[ne + e];
        }
        unsigned bit = 1u << (col & 31);
        unsigned old = atomicOr(&g_A[row * NW + (col >> 5)], bit);
        if (!(old & bit)) {
            int pp = atomicAdd(&g_cnt[row], 1);
            if (pp < CAP) g_nbr[row * CAP + pp] = (unsigned short)col;
        }
        float v = 0.69314718055994531f * g_a0[col];
        long long q = __float2ll_rn(v * 4294967296.0f);
        atomicAdd((unsigned long long*)&g_stepq[row], (unsigned long long)q);
    }

    grid_barrier(&g_sync1, gridDim.x);
    hop_body(0, out, vsh, seg, part, blockIdx.x);
    grid_barrier(&g_sync2, gridDim.x);
    hop_body(1, out, vsh, seg, part, blockIdx.x);
}

// ---------------- launch ----------------------------------------------------
extern "C" void kernel_launch(void* const* d_in, const int* in_sizes, int n_in,
                              void* d_out, int out_size) {
    const float* coeffs = (const float*)d_in[0];
    const void*  ei     = d_in[1];
    const float* W0     = (const float*)d_in[2];
    const float* b0     = (const float*)d_in[3];
    const float* W1     = (const float*)d_in[4];
    const float* W2     = (const float*)d_in[5];
    const float* W3     = (const float*)d_in[6];
    const float* b3     = (const float*)d_in[7];
    float* out = (float*)d_out;

    const int ne = in_sizes[1] / 2;

    const int prep_blocks = (N * NW + 3 * 16384) / 256 + 1;
    prep_kernel<<<prep_blocks, 256>>>(W0, W1, W2, ei);

    mlp_kernel<<<N / MLP_R, 128>>>(coeffs, b0, W3, b3);

    mega_kernel<<<MEGA_B, 512>>>(ei, ne, out);
}

// round 13
// speedup vs baseline: 1.0348x; 1.0348x over previous
#include <cuda_runtime.h>
#include <math.h>

#define N      4096
#define D      128
#define NW     128          // 4096 bits / 32
#define MLP_R  16           // rows per MLP block
#define XSTRIDE 36          // dup-x smem row stride (floats)
#define CAP    192          // per-row unique-neighbor list capacity
#define GS     33           // padded stride for a 32-float group in smem
#define MEGA_B 512          // mega kernel blocks (all resident: 148*4=592)
#define PREP_ZB 240         // prep zeroing blocks
#define INV232 2.3283064365386963e-10f   // 2^-32

// ---------------- scratch (device globals) ----------------------------------
__device__ unsigned       g_A  [N * NW];
__device__ unsigned       g_A2 [N * NW];
__device__ unsigned short g_nbr[N * CAP];   // unique neighbor lists
__device__ int            g_cnt[N];
__device__ float          g_Wt [3 * D * D]; // pre-transposed weights, k-major
__device__ float          g_a0[N];
__device__ float          g_av2[N];
__device__ long long      g_stepq[N];
__device__ float          g_step[N];
__device__ int            g_is64;
__device__ unsigned       g_sync1, g_sync2; // grid barriers (reset by prep)

#define FMA2(acc, w, x) asm("fma.rn.f32x2 %0, %1, %2, %0;" : "+l"(acc) : "l"(w), "l"(x))
union U64F2 { unsigned long long u; float2 f; };

// ---------------- grid-wide barrier (all blocks provably resident) ----------
__device__ __forceinline__ void grid_barrier(unsigned* cnt, unsigned nblocks) {
    __syncthreads();
    if (threadIdx.x == 0) {
        __threadfence();                      // release (cumulative)
        atomicAdd(cnt, 1u);
        unsigned v;
        do {
            asm volatile("ld.acquire.gpu.global.u32 %0, [%1];"
                         : "=r"(v) : "l"(cnt));
        } while (v < nblocks);
    }
    __syncthreads();
}

// ---------------- prep: vectorized zero + tiled transpose + detect ----------
// grid = PREP_ZB + 16 + 1 blocks, 256 threads.
__global__ void prep_kernel(const float* __restrict__ W0,
                            const float* __restrict__ W1,
                            const float* __restrict__ W2,
                            const void* __restrict__ ei) {
    const int b   = blockIdx.x;
    const int tid = threadIdx.x;

    if (b < PREP_ZB) {
        // ---- bulk zero via uint4 ----
        const uint4 z = make_uint4(0u, 0u, 0u, 0u);
        uint4* pA = (uint4*)g_A;                       // 131072 uint4
        for (int i = b * 256 + tid; i < (N * NW) / 4; i += PREP_ZB * 256)
            pA[i] = z;
        uint4* pS = (uint4*)g_stepq;                   // 2048 uint4
        for (int i = b * 256 + tid; i < N / 2; i += PREP_ZB * 256)
            pS[i] = z;
        uint4* pC = (uint4*)g_cnt;                     // 1024 uint4
        for (int i = b * 256 + tid; i < N / 4; i += PREP_ZB * 256)
            pC[i] = z;
        if (b == 0 && tid == 0) { g_sync1 = 0u; g_sync2 = 0u; }
    } else if (b < PREP_ZB + 16) {
        // ---- transpose W0..W2 into g_Wt (k-major) via 32x32 smem tiles ----
        __shared__ float tile[32][33];
        const int t  = b - PREP_ZB;          // 0..15
        const int I  = t >> 2;               // c-tile
        const int J  = t & 3;                // k-tile
        const int tx = tid & 31;
        const int ty = tid >> 5;             // 0..7
        #pragma unroll
        for (int m = 0; m < 3; m++) {
            const float* W = (m == 0) ? W0 : (m == 1 ? W1 : W2);
            #pragma unroll
            for (int rr = 0; rr < 4; rr++) {
                int row = ty + rr * 8;       // c within tile
                tile[row][tx] = W[(I * 32 + row) * 128 + J * 32 + tx];
            }
            __syncthreads();
            #pragma unroll
            for (int rr = 0; rr < 4; rr++) {
                int row = ty + rr * 8;       // k within tile
                g_Wt[m * 16384 + (J * 32 + row) * 128 + I * 32 + tx] = tile[tx][row];
            }
            __syncthreads();
        }
    } else {
        // ---- dtype detection ----
        __shared__ int bad;
        if (tid == 0) bad = 0;
        __syncthreads();
        const long long* p = (const long long*)ei;
        for (int i = tid; i < 2048; i += blockDim.x) {
            long long v = p[i];
            if (v < 0 || v >= N) bad = 1;
        }
        __syncthreads();
        if (tid == 0) g_is64 = bad ? 0 : 1;
    }
}

// ---------------- fused MLP: 3 x (GEMM+ReLU) + final dot, one kernel --------
__global__ __launch_bounds__(128, 4)
void mlp_kernel(const float* __restrict__ coeffs,
                const float* __restrict__ b0,
                const float* __restrict__ W3,
                const float* __restrict__ b3) {
    __shared__ float xa[128 * XSTRIDE];
    __shared__ float xb[128 * XSTRIDE];

    const int tid = threadIdx.x;
    const int r0  = blockIdx.x * MLP_R;
    const int rg  = tid >> 4;     // 8 row-groups of 2 rows
    const int cg  = tid & 15;     // 16 col-groups

    #pragma unroll
    for (int it = 0; it < 4; it++) {
        int idx = it * 128 + tid;
        int r  = idx >> 5;
        int kq = idx & 31;
        float4 v = *(const float4*)&coeffs[(r0 + r) * 128 + kq * 4];
        float vv[4] = {v.x, v.y, v.z, v.w};
        #pragma unroll
        for (int q = 0; q < 4; q++)
            *(float2*)&xa[(kq * 4 + q) * XSTRIDE + 2 * r] = make_float2(vv[q], vv[q]);
    }
    __syncthreads();

    float* Xin  = xa;
    float* Xout = xb;

    #pragma unroll
    for (int layer = 0; layer < 3; layer++) {
        const float* Wl = g_Wt + layer * 16384;

        unsigned long long a0p[4], a1p[4];
        #pragma unroll
        for (int j = 0; j < 4; j++) { a0p[j] = 0ull; a1p[j] = 0ull; }

        #pragma unroll 8
        for (int k = 0; k < 128; k++) {
            ulonglong2 xx = *(const ulonglong2*)&Xin[k * XSTRIDE + rg * 4];
            const float* wrow = Wl + k * 128 + cg * 2;
            unsigned long long w0 = *(const unsigned long long*)(wrow);
            unsigned long long w1 = *(const unsigned long long*)(wrow + 32);
            unsigned long long w2 = *(const unsigned long long*)(wrow + 64);
            unsigned long long w3 = *(const unsigned long long*)(wrow + 96);
            FMA2(a0p[0], w0, xx.x); FMA2(a1p[0], w0, xx.y);
            FMA2(a0p[1], w1, xx.x); FMA2(a1p[1], w1, xx.y);
            FMA2(a0p[2], w2, xx.x); FMA2(a1p[2], w2, xx.y);
            FMA2(a0p[3], w3, xx.x); FMA2(a1p[3], w3, xx.y);
        }

        float o0[8], o1[8];
        #pragma unroll
        for (int j = 0; j < 4; j++) {
            U64F2 u0, u1; u0.u = a0p[j]; u1.u = a1p[j];
            o0[2 * j] = u0.f.x; o0[2 * j + 1] = u0.f.y;
            o1[2 * j] = u1.f.x; o1[2 * j + 1] = u1.f.y;
        }
        if (layer == 0) {
            #pragma unroll
            for (int j = 0; j < 4; j++) {
                float2 bb = *(const float2*)&b0[32 * j + cg * 2];
                o0[2 * j] += bb.x; o0[2 * j + 1] += bb.y;
                o1[2 * j] += bb.x; o1[2 * j + 1] += bb.y;
            }
        }
        #pragma unroll
        for (int j = 0; j < 8; j++) {
            o0[j] = fmaxf(o0[j], 0.f);
            o1[j] = fmaxf(o1[j], 0.f);
        }

        if (layer < 2) {
            #pragma unroll
            for (int j = 0; j < 4; j++) {
                int k0 = cg * 2 + 32 * j;
                *(float2*)&Xout[(k0    ) * XSTRIDE + 4 * rg    ] = make_float2(o0[2*j],   o0[2*j]);
                *(float2*)&Xout[(k0 + 1) * XSTRIDE + 4 * rg    ] = make_float2(o0[2*j+1], o0[2*j+1]);
                *(float2*)&Xout[(k0    ) * XSTRIDE + 4 * rg + 2] = make_float2(o1[2*j],   o1[2*j]);
                *(float2*)&Xout[(k0 + 1) * XSTRIDE + 4 * rg + 2] = make_float2(o1[2*j+1], o1[2*j+1]);
            }
            __syncthreads();
            float* tmp = Xin; Xin = Xout; Xout = tmp;
        } else {
            float p0 = 0.f, p1 = 0.f;
            #pragma unroll
            for (int j = 0; j < 4; j++) {
                float2 w3v = *(const float2*)&W3[32 * j + cg * 2];
                p0 = fmaf(o0[2*j], w3v.x, fmaf(o0[2*j+1], w3v.y, p0));
                p1 = fmaf(o1[2*j], w3v.x, fmaf(o1[2*j+1], w3v.y, p1));
            }
            #pragma unroll
            for (int off = 8; off; off >>= 1) {
                p0 += __shfl_down_sync(0xffffffffu, p0, off, 16);
                p1 += __shfl_down_sync(0xffffffffu, p1, off, 16);
            }
            if (cg == 0) {
                float bb = b3[0];
                g_a0[r0 + rg * 2]     = p0 + bb;
                g_a0[r0 + rg * 2 + 1] = p1 + bb;
            }
        }
    }
}

// ---------------- hop body (shared by both phases) ----------------------------
__device__ __forceinline__ void hop_body(int phase, float* __restrict__ out_final,
                                         float* vsh, float* seg, float* part,
                                         int blk) {
    const unsigned* M = phase ? g_A2 : g_A;

    const int tid  = threadIdx.x;
    const int wid  = tid >> 5;
    const int lane = tid & 31;
    const int r    = wid >> 1;          // row within block (0..7)
    const int h    = wid & 1;           // column half (0..1)
    const int i    = blk * 8 + r;

    // ---- 1. OR over neighbor rows via unique neighbor list ------------------
    const int woff = h * 64 + 2 * lane;              // this lane's word pair
    const int cnt  = g_cnt[i];
    unsigned ax = 0u, ay = 0u;

    if (cnt <= CAP) {
        const unsigned short* nb = g_nbr + i * CAP;
        int j = 0;
        for (; j + 8 <= cnt; j += 8) {
            uint4 nn = *(const uint4*)&nb[j];        // 8 ushorts, uniform
            int n0 = nn.x & 0xffff, n1 = nn.x >> 16;
            int n2 = nn.y & 0xffff, n3 = nn.y >> 16;
            int n4 = nn.z & 0xffff, n5 = nn.z >> 16;
            int n6 = nn.w & 0xffff, n7 = nn.w >> 16;
            uint2 q0 = __ldg((const uint2*)&M[n0 * NW + woff]);
            uint2 q1 = __ldg((const uint2*)&M[n1 * NW + woff]);
            uint2 q2 = __ldg((const uint2*)&M[n2 * NW + woff]);
            uint2 q3 = __ldg((const uint2*)&M[n3 * NW + woff]);
            uint2 q4 = __ldg((const uint2*)&M[n4 * NW + woff]);
            uint2 q5 = __ldg((const uint2*)&M[n5 * NW + woff]);
            uint2 q6 = __ldg((const uint2*)&M[n6 * NW + woff]);
            uint2 q7 = __ldg((const uint2*)&M[n7 * NW + woff]);
            ax |= ((q0.x | q1.x) | (q2.x | q3.x)) | ((q4.x | q5.x) | (q6.x | q7.x));
            ay |= ((q0.y | q1.y) | (q2.y | q3.y)) | ((q4.y | q5.y) | (q6.y | q7.y));
        }
        for (; j < cnt; j++) {
            int n = nb[j];
            uint2 q = __ldg((const uint2*)&M[n * NW + woff]);
            ax |= q.x; ay |= q.y;
        }
    } else {
        // fallback: bit-walk over the adjacency row (pathological degrees)
        const uint4* Arow = (const uint4*)&g_A[i * NW];
        for (int c = 0; c < 32; c++) {
            uint4 mw = __ldg(&Arow[c]);
            int jb = c * 128;
            unsigned m;
            m = mw.x; while (m) { int b = __ffs((int)m) - 1; m &= m - 1;
                uint2 q = *(const uint2*)&M[(jb + b) * NW + woff]; ax |= q.x; ay |= q.y; }
            m = mw.y; while (m) { int b = __ffs((int)m) - 1; m &= m - 1;
                uint2 q = *(const uint2*)&M[(jb + 32 + b) * NW + woff]; ax |= q.x; ay |= q.y; }
            m = mw.z; while (m) { int b = __ffs((int)m) - 1; m &= m - 1;
                uint2 q = *(const uint2*)&M[(jb + 64 + b) * NW + woff]; ax |= q.x; ay |= q.y; }
            m = mw.w; while (m) { int b = __ffs((int)m) - 1; m &= m - 1;
                uint2 q = *(const uint2*)&M[(jb + 96 + b) * NW + woff]; ax |= q.x; ay |= q.y; }
        }
    }

    if (!phase) *(uint2*)&g_A2[i * NW + woff] = make_uint2(ax, ay);

    // ---- 2. load angle vector, store to padded smem + per-group sums -------
    {
        float vv[8];
        if (phase) {
            float4 u0 = *(const float4*)&g_av2[tid * 8];
            float4 u1 = *(const float4*)&g_av2[tid * 8 + 4];
            vv[0]=u0.x; vv[1]=u0.y; vv[2]=u0.z; vv[3]=u0.w;
            vv[4]=u1.x; vv[5]=u1.y; vv[6]=u1.z; vv[7]=u1.w;
        } else {
            float4 u0 = *(const float4*)&g_a0[tid * 8];
            float4 u1 = *(const float4*)&g_a0[tid * 8 + 4];
            const longlong2* sq = (const longlong2*)g_stepq + tid * 4;
            longlong2 q0 = sq[0], q1 = sq[1], q2 = sq[2], q3 = sq[3];
            vv[0] = u0.x + __ll2float_rn(q0.x) * INV232;
            vv[1] = u0.y + __ll2float_rn(q0.y) * INV232;
            vv[2] = u0.z + __ll2float_rn(q1.x) * INV232;
            vv[3] = u0.w + __ll2float_rn(q1.y) * INV232;
            vv[4] = u1.x + __ll2float_rn(q2.x) * INV232;
            vv[5] = u1.y + __ll2float_rn(q2.y) * INV232;
            vv[6] = u1.z + __ll2float_rn(q3.x) * INV232;
            vv[7] = u1.w + __ll2float_rn(q3.y) * INV232;
        }
        const int g  = tid >> 2;            // 32-float group (one per 4 threads)
        const int o0 = (tid & 3) * 8;       // offset within group
        float s = 0.f;
        #pragma unroll
        for (int q = 0; q < 8; q++) {
            vsh[g * GS + o0 + q] = vv[q];
            s += vv[q];
        }
        s += __shfl_down_sync(0xffffffffu, s, 2, 4);
        s += __shfl_down_sync(0xffffffffu, s, 1, 4);
        if ((tid & 3) == 0) seg[g] = s;
    }
    __syncthreads();

    // ---- 3. gated sum over this lane's two 32-float groups ------------------
    const float* base0 = vsh + woff * GS;          // group woff
    const float* base1 = vsh + (woff + 1) * GS;    // group woff+1
    int pc = __popc(ax) + __popc(ay);
    float sv;
    if (pc > 32) {
        sv = seg[woff] + seg[woff + 1];
        unsigned m;
        m = ~ax; while (m) { int b = __ffs((int)m) - 1; m &= m - 1; sv -= base0[b]; }
        m = ~ay; while (m) { int b = __ffs((int)m) - 1; m &= m - 1; sv -= base1[b]; }
    } else {
        sv = 0.f;
        unsigned m;
        m = ax; while (m) { int b = __ffs((int)m) - 1; m &= m - 1; sv += base0[b]; }
        m = ay; while (m) { int b = __ffs((int)m) - 1; m &= m - 1; sv += base1[b]; }
    }
    #pragma unroll
    for (int o = 16; o; o >>= 1) sv += __shfl_down_sync(0xffffffffu, sv, o);
    if (lane == 0) part[wid] = sv;
    __syncthreads();

    // ---- 4. combine halves + epilogue (threads 0..7 handle rows 0..7) ------
    if (tid < 8) {
        const int ii = blk * 8 + tid;
        float vi = vsh[(ii >> 5) * GS + (ii & 31)];
        float tot = part[2 * tid] + part[2 * tid + 1];
        if (!phase) {
            float s1 = __ll2float_rn(g_stepq[ii]) * INV232;
            float ns = s1 + 1.0986122886681098f * tot;            // ln 3
            g_step[ii] = ns;
            g_av2[ii]  = vi + ns;                                  // a1 + step
        } else {
            out_final[ii] = vi + g_step[ii] + 1.3862943611198906f * tot; // ln 4
        }
    }
}

// ---------------- mega: edge scatter + grid barrier + hop0 + barrier + hop1 --
__global__ __launch_bounds__(512, 4)
void mega_kernel(const void* __restrict__ ei, int ne, float* __restrict__ out) {
    __shared__ float vsh[128 * GS];
    __shared__ float seg[128];
    __shared__ float part[16];

    // ---- edge part: bitset + unique neighbor list + hop-1 scatter ----------
    const int is64   = g_is64;
    const int stride = gridDim.x * blockDim.x;
    for (int e = blockIdx.x * blockDim.x + threadIdx.x; e < ne; e += stride) {
        int row, col;
        if (is64) {
            const long long* p = (const long long*)ei;
            row = (int)p[e];
            col = (int)p[ne + e];
        } else {
            const int* p = (const int*)ei;
            row = p[e];
            col = p[ne + e];
        }
        unsigned bit = 1u << (col & 31);
        unsigned old = atomicOr(&g_A[row * NW + (col >> 5)], bit);
        if (!(old & bit)) {
            int pp = atomicAdd(&g_cnt[row], 1);
            if (pp < CAP) g_nbr[row * CAP + pp] = (unsigned short)col;
        }
        float v = 0.69314718055994531f * g_a0[col];
        long long q = __float2ll_rn(v * 4294967296.0f);
        atomicAdd((unsigned long long*)&g_stepq[row], (unsigned long long)q);
    }

    grid_barrier(&g_sync1, gridDim.x);
    hop_body(0, out, vsh, seg, part, blockIdx.x);
    grid_barrier(&g_sync2, gridDim.x);
    hop_body(1, out, vsh, seg, part, blockIdx.x);
}

// ---------------- launch ----------------------------------------------------
extern "C" void kernel_launch(void* const* d_in, const int* in_sizes, int n_in,
                              void* d_out, int out_size) {
    const float* coeffs = (const float*)d_in[0];
    const void*  ei     = d_in[1];
    const float* W0     = (const float*)d_in[2];
    const float* b0     = (const float*)d_in[3];
    const float* W1     = (const float*)d_in[4];
    const float* W2     = (const float*)d_in[5];
    const float* W3     = (const float*)d_in[6];
    const float* b3     = (const float*)d_in[7];
    float* out = (float*)d_out;

    const int ne = in_sizes[1] / 2;

    prep_kernel<<<PREP_ZB + 16 + 1, 256>>>(W0, W1, W2, ei);

    mlp_kernel<<<N / MLP_R, 128>>>(coeffs, b0, W3, b3);

    mega_kernel<<<MEGA_B, 512>>>(ei, ne, out);
}

// round 14
// speedup vs baseline: 1.0354x; 1.0006x over previous
#include <cuda_runtime.h>
#include <math.h>

#define N      4096
#define D      128
#define NW     128          // 4096 bits / 32
#define MLP_R  16           // rows per MLP block
#define XSTRIDE 36          // dup-x smem row stride (floats)
#define CAP    192          // per-row unique-neighbor list capacity
#define GS     33           // padded stride for a 32-float group in smem
#define MEGA_B 512          // mega kernel blocks (all resident: 148*4=592)
#define INV232 2.3283064365386963e-10f   // 2^-32

// ---------------- scratch (device globals) ----------------------------------
__device__ unsigned       g_A  [N * NW];
__device__ unsigned       g_A2 [N * NW];
__device__ unsigned short g_nbr[N * CAP];   // unique neighbor lists
__device__ int            g_cnt[N];
__device__ float          g_Wt [3 * D * D]; // pre-transposed weights, k-major
__device__ float          g_a0[N];
__device__ float          g_av2[N];
__device__ long long      g_stepq[N];
__device__ float          g_step[N];
__device__ int            g_is64;
__device__ unsigned       g_sync0;          // mlp_mega barrier (reset by mega)
__device__ unsigned       g_sync1, g_sync2; // mega barriers (reset by mlp_mega)

#define FMA2(acc, w, x) asm("fma.rn.f32x2 %0, %1, %2, %0;" : "+l"(acc) : "l"(w), "l"(x))
union U64F2 { unsigned long long u; float2 f; };

// ---------------- grid-wide barrier (all blocks provably resident) ----------
__device__ __forceinline__ void grid_barrier(unsigned* cnt, unsigned nblocks) {
    __syncthreads();
    if (threadIdx.x == 0) {
        __threadfence();                      // release (cumulative)
        atomicAdd(cnt, 1u);
        unsigned v;
        do {
            asm volatile("ld.acquire.gpu.global.u32 %0, [%1];"
                         : "=r"(v) : "l"(cnt));
        } while (v < nblocks);
    }
    __syncthreads();
}

// ---------------- mlp_mega: prep (zero+transpose+detect) + barrier + MLP ----
// grid = 257 blocks x 128 threads. Blocks 0..255: zero slices (+48 transpose
// tiles), block 256: dtype detect. Then grid barrier, then MLP (blocks 0..255).
__global__ __launch_bounds__(128, 4)
void mlp_mega_kernel(const float* __restrict__ coeffs,
                     const float* __restrict__ W0,
                     const float* __restrict__ b0,
                     const float* __restrict__ W1,
                     const float* __restrict__ W2,
                     const float* __restrict__ W3,
                     const float* __restrict__ b3,
                     const void* __restrict__ ei) {
    __shared__ float xa[128 * XSTRIDE];
    __shared__ float xb[128 * XSTRIDE];

    const int b   = blockIdx.x;
    const int tid = threadIdx.x;

    if (b == 0 && tid == 0) { g_sync1 = 0u; g_sync2 = 0u; }  // for mega (later)

    if (b < 256) {
        // ---- vectorized zero: g_A (131072 uint4), g_stepq, g_cnt ----
        const uint4 z = make_uint4(0u, 0u, 0u, 0u);
        const int idx = b * 128 + tid;            // 0..32767
        uint4* pA = (uint4*)g_A;
        #pragma unroll
        for (int q = 0; q < 4; q++) pA[idx + q * 32768] = z;
        if (idx < 2048) ((uint4*)g_stepq)[idx] = z;
        if (idx < 1024) ((uint4*)g_cnt)[idx]   = z;

        // ---- transpose W0..W2 into g_Wt (blocks 0..47, one 32x32 tile) ----
        if (b < 48) {
            __shared__ float tile[32][33];
            const int m = b >> 4;                 // matrix 0..2
            const int t = b & 15;
            const int I = t >> 2;                 // c-tile
            const int J = t & 3;                  // k-tile
            const int tx = tid & 31;
            const int ty = tid >> 5;              // 0..3
            const float* W = (m == 0) ? W0 : (m == 1 ? W1 : W2);
            #pragma unroll
            for (int rr = 0; rr < 8; rr++) {
                int row = ty + rr * 4;            // c within tile
                tile[row][tx] = W[(I * 32 + row) * 128 + J * 32 + tx];
            }
            __syncthreads();
            #pragma unroll
            for (int rr = 0; rr < 8; rr++) {
                int row = ty + rr * 4;            // k within tile
                g_Wt[m * 16384 + (J * 32 + row) * 128 + I * 32 + tx] = tile[tx][row];
            }
        }
    } else {
        // ---- dtype detection ----
        __shared__ int bad;
        if (tid == 0) bad = 0;
        __syncthreads();
        const long long* p = (const long long*)ei;
        for (int i = tid; i < 2048; i += blockDim.x) {
            long long v = p[i];
            if (v < 0 || v >= N) bad = 1;
        }
        __syncthreads();
        if (tid == 0) g_is64 = bad ? 0 : 1;
    }

    grid_barrier(&g_sync0, gridDim.x);
    if (b >= 256) return;

    // ================= MLP: 3 x (GEMM+ReLU) + fused final dot ===============
    const int r0 = b * MLP_R;
    const int rg = tid >> 4;     // 8 row-groups of 2 rows
    const int cg = tid & 15;     // 16 col-groups

    #pragma unroll
    for (int it = 0; it < 4; it++) {
        int idx = it * 128 + tid;
        int r  = idx >> 5;
        int kq = idx & 31;
        float4 v = *(const float4*)&coeffs[(r0 + r) * 128 + kq * 4];
        float vv[4] = {v.x, v.y, v.z, v.w};
        #pragma unroll
        for (int q = 0; q < 4; q++)
            *(float2*)&xa[(kq * 4 + q) * XSTRIDE + 2 * r] = make_float2(vv[q], vv[q]);
    }
    __syncthreads();

    float* Xin  = xa;
    float* Xout = xb;

    #pragma unroll
    for (int layer = 0; layer < 3; layer++) {
        const float* Wl = g_Wt + layer * 16384;

        unsigned long long a0p[4], a1p[4];
        #pragma unroll
        for (int j = 0; j < 4; j++) { a0p[j] = 0ull; a1p[j] = 0ull; }

        #pragma unroll 8
        for (int k = 0; k < 128; k++) {
            ulonglong2 xx = *(const ulonglong2*)&Xin[k * XSTRIDE + rg * 4];
            const float* wrow = Wl + k * 128 + cg * 2;
            unsigned long long w0 = *(const unsigned long long*)(wrow);
            unsigned long long w1 = *(const unsigned long long*)(wrow + 32);
            unsigned long long w2 = *(const unsigned long long*)(wrow + 64);
            unsigned long long w3 = *(const unsigned long long*)(wrow + 96);
            FMA2(a0p[0], w0, xx.x); FMA2(a1p[0], w0, xx.y);
            FMA2(a0p[1], w1, xx.x); FMA2(a1p[1], w1, xx.y);
            FMA2(a0p[2], w2, xx.x); FMA2(a1p[2], w2, xx.y);
            FMA2(a0p[3], w3, xx.x); FMA2(a1p[3], w3, xx.y);
        }

        float o0[8], o1[8];
        #pragma unroll
        for (int j = 0; j < 4; j++) {
            U64F2 u0, u1; u0.u = a0p[j]; u1.u = a1p[j];
            o0[2 * j] = u0.f.x; o0[2 * j + 1] = u0.f.y;
            o1[2 * j] = u1.f.x; o1[2 * j + 1] = u1.f.y;
        }
        if (layer == 0) {
            #pragma unroll
            for (int j = 0; j < 4; j++) {
                float2 bb = *(const float2*)&b0[32 * j + cg * 2];
                o0[2 * j] += bb.x; o0[2 * j + 1] += bb.y;
                o1[2 * j] += bb.x; o1[2 * j + 1] += bb.y;
            }
        }
        #pragma unroll
        for (int j = 0; j < 8; j++) {
            o0[j] = fmaxf(o0[j], 0.f);
            o1[j] = fmaxf(o1[j], 0.f);
        }

        if (layer < 2) {
            #pragma unroll
            for (int j = 0; j < 4; j++) {
                int k0 = cg * 2 + 32 * j;
                *(float2*)&Xout[(k0    ) * XSTRIDE + 4 * rg    ] = make_float2(o0[2*j],   o0[2*j]);
                *(float2*)&Xout[(k0 + 1) * XSTRIDE + 4 * rg    ] = make_float2(o0[2*j+1], o0[2*j+1]);
                *(float2*)&Xout[(k0    ) * XSTRIDE + 4 * rg + 2] = make_float2(o1[2*j],   o1[2*j]);
                *(float2*)&Xout[(k0 + 1) * XSTRIDE + 4 * rg + 2] = make_float2(o1[2*j+1], o1[2*j+1]);
            }
            __syncthreads();
            float* tmp = Xin; Xin = Xout; Xout = tmp;
        } else {
            float p0 = 0.f, p1 = 0.f;
            #pragma unroll
            for (int j = 0; j < 4; j++) {
                float2 w3v = *(const float2*)&W3[32 * j + cg * 2];
                p0 = fmaf(o0[2*j], w3v.x, fmaf(o0[2*j+1], w3v.y, p0));
                p1 = fmaf(o1[2*j], w3v.x, fmaf(o1[2*j+1], w3v.y, p1));
            }
            #pragma unroll
            for (int off = 8; off; off >>= 1) {
                p0 += __shfl_down_sync(0xffffffffu, p0, off, 16);
                p1 += __shfl_down_sync(0xffffffffu, p1, off, 16);
            }
            if (cg == 0) {
                float bb = b3[0];
                g_a0[r0 + rg * 2]     = p0 + bb;
                g_a0[r0 + rg * 2 + 1] = p1 + bb;
            }
        }
    }
}

// ---------------- hop body (shared by both phases) ----------------------------
__device__ __forceinline__ void hop_body(int phase, float* __restrict__ out_final,
                                         float* vsh, float* seg, float* part,
                                         int blk) {
    const unsigned* M = phase ? g_A2 : g_A;

    const int tid  = threadIdx.x;
    const int wid  = tid >> 5;
    const int lane = tid & 31;
    const int r    = wid >> 1;          // row within block (0..7)
    const int h    = wid & 1;           // column half (0..1)
    const int i    = blk * 8 + r;

    // ---- 1. OR over neighbor rows via unique neighbor list ------------------
    const int woff = h * 64 + 2 * lane;              // this lane's word pair
    const int cnt  = g_cnt[i];
    unsigned ax = 0u, ay = 0u;

    if (cnt <= CAP) {
        const unsigned short* nb = g_nbr + i * CAP;
        int j = 0;
        for (; j + 8 <= cnt; j += 8) {
            uint4 nn = *(const uint4*)&nb[j];        // 8 ushorts, uniform
            int n0 = nn.x & 0xffff, n1 = nn.x >> 16;
            int n2 = nn.y & 0xffff, n3 = nn.y >> 16;
            int n4 = nn.z & 0xffff, n5 = nn.z >> 16;
            int n6 = nn.w & 0xffff, n7 = nn.w >> 16;
            uint2 q0 = __ldg((const uint2*)&M[n0 * NW + woff]);
            uint2 q1 = __ldg((const uint2*)&M[n1 * NW + woff]);
            uint2 q2 = __ldg((const uint2*)&M[n2 * NW + woff]);
            uint2 q3 = __ldg((const uint2*)&M[n3 * NW + woff]);
            uint2 q4 = __ldg((const uint2*)&M[n4 * NW + woff]);
            uint2 q5 = __ldg((const uint2*)&M[n5 * NW + woff]);
            uint2 q6 = __ldg((const uint2*)&M[n6 * NW + woff]);
            uint2 q7 = __ldg((const uint2*)&M[n7 * NW + woff]);
            ax |= ((q0.x | q1.x) | (q2.x | q3.x)) | ((q4.x | q5.x) | (q6.x | q7.x));
            ay |= ((q0.y | q1.y) | (q2.y | q3.y)) | ((q4.y | q5.y) | (q6.y | q7.y));
        }
        for (; j < cnt; j++) {
            int n = nb[j];
            uint2 q = __ldg((const uint2*)&M[n * NW + woff]);
            ax |= q.x; ay |= q.y;
        }
    } else {
        // fallback: bit-walk over the adjacency row (pathological degrees)
        const uint4* Arow = (const uint4*)&g_A[i * NW];
        for (int c = 0; c < 32; c++) {
            uint4 mw = __ldg(&Arow[c]);
            int jb = c * 128;
            unsigned m;
            m = mw.x; while (m) { int b = __ffs((int)m) - 1; m &= m - 1;
                uint2 q = *(const uint2*)&M[(jb + b) * NW + woff]; ax |= q.x; ay |= q.y; }
            m = mw.y; while (m) { int b = __ffs((int)m) - 1; m &= m - 1;
                uint2 q = *(const uint2*)&M[(jb + 32 + b) * NW + woff]; ax |= q.x; ay |= q.y; }
            m = mw.z; while (m) { int b = __ffs((int)m) - 1; m &= m - 1;
                uint2 q = *(const uint2*)&M[(jb + 64 + b) * NW + woff]; ax |= q.x; ay |= q.y; }
            m = mw.w; while (m) { int b = __ffs((int)m) - 1; m &= m - 1;
                uint2 q = *(const uint2*)&M[(jb + 96 + b) * NW + woff]; ax |= q.x; ay |= q.y; }
        }
    }

    if (!phase) *(uint2*)&g_A2[i * NW + woff] = make_uint2(ax, ay);

    // ---- 2. load angle vector, store to padded smem + per-group sums -------
    {
        float vv[8];
        if (phase) {
            float4 u0 = *(const float4*)&g_av2[tid * 8];
            float4 u1 = *(const float4*)&g_av2[tid * 8 + 4];
            vv[0]=u0.x; vv[1]=u0.y; vv[2]=u0.z; vv[3]=u0.w;
            vv[4]=u1.x; vv[5]=u1.y; vv[6]=u1.z; vv[7]=u1.w;
        } else {
            float4 u0 = *(const float4*)&g_a0[tid * 8];
            float4 u1 = *(const float4*)&g_a0[tid * 8 + 4];
            const longlong2* sq = (const longlong2*)g_stepq + tid * 4;
            longlong2 q0 = sq[0], q1 = sq[1], q2 = sq[2], q3 = sq[3];
            vv[0] = u0.x + __ll2float_rn(q0.x) * INV232;
            vv[1] = u0.y + __ll2float_rn(q0.y) * INV232;
            vv[2] = u0.z + __ll2float_rn(q1.x) * INV232;
            vv[3] = u0.w + __ll2float_rn(q1.y) * INV232;
            vv[4] = u1.x + __ll2float_rn(q2.x) * INV232;
            vv[5] = u1.y + __ll2float_rn(q2.y) * INV232;
            vv[6] = u1.z + __ll2float_rn(q3.x) * INV232;
            vv[7] = u1.w + __ll2float_rn(q3.y) * INV232;
        }
        const int g  = tid >> 2;            // 32-float group (one per 4 threads)
        const int o0 = (tid & 3) * 8;       // offset within group
        float s = 0.f;
        #pragma unroll
        for (int q = 0; q < 8; q++) {
            vsh[g * GS + o0 + q] = vv[q];
            s += vv[q];
        }
        s += __shfl_down_sync(0xffffffffu, s, 2, 4);
        s += __shfl_down_sync(0xffffffffu, s, 1, 4);
        if ((tid & 3) == 0) seg[g] = s;
    }
    __syncthreads();

    // ---- 3. gated sum over this lane's two 32-float groups ------------------
    const float* base0 = vsh + woff * GS;          // group woff
    const float* base1 = vsh + (woff + 1) * GS;    // group woff+1
    int pc = __popc(ax) + __popc(ay);
    float sv;
    if (pc > 32) {
        sv = seg[woff] + seg[woff + 1];
        unsigned m;
        m = ~ax; while (m) { int b = __ffs((int)m) - 1; m &= m - 1; sv -= base0[b]; }
        m = ~ay; while (m) { int b = __ffs((int)m) - 1; m &= m - 1; sv -= base1[b]; }
    } else {
        sv = 0.f;
        unsigned m;
        m = ax; while (m) { int b = __ffs((int)m) - 1; m &= m - 1; sv += base0[b]; }
        m = ay; while (m) { int b = __ffs((int)m) - 1; m &= m - 1; sv += base1[b]; }
    }
    #pragma unroll
    for (int o = 16; o; o >>= 1) sv += __shfl_down_sync(0xffffffffu, sv, o);
    if (lane == 0) part[wid] = sv;
    __syncthreads();

    // ---- 4. combine halves + epilogue (threads 0..7 handle rows 0..7) ------
    if (tid < 8) {
        const int ii = blk * 8 + tid;
        float vi = vsh[(ii >> 5) * GS + (ii & 31)];
        float tot = part[2 * tid] + part[2 * tid + 1];
        if (!phase) {
            float s1 = __ll2float_rn(g_stepq[ii]) * INV232;
            float ns = s1 + 1.0986122886681098f * tot;            // ln 3
            g_step[ii] = ns;
            g_av2[ii]  = vi + ns;                                  // a1 + step
        } else {
            out_final[ii] = vi + g_step[ii] + 1.3862943611198906f * tot; // ln 4
        }
    }
}

// ---------------- mega: edge scatter + grid barrier + hop0 + barrier + hop1 --
__global__ __launch_bounds__(512, 4)
void mega_kernel(const void* __restrict__ ei, int ne, float* __restrict__ out) {
    __shared__ float vsh[128 * GS];
    __shared__ float seg[128];
    __shared__ float part[16];

    if (blockIdx.x == 0 && threadIdx.x == 0) g_sync0 = 0u;  // for next replay

    // ---- edge part: bitset + unique neighbor list + hop-1 scatter ----------
    const int is64   = g_is64;
    const int stride = gridDim.x * blockDim.x;
    for (int e = blockIdx.x * blockDim.x + threadIdx.x; e < ne; e += stride) {
        int row, col;
        if (is64) {
            const long long* p = (const long long*)ei;
            row = (int)p[e];
            col = (int)p[ne + e];
        } else {
            const int* p = (const int*)ei;
            row = p[e];
            col = p[ne + e];
        }
        unsigned bit = 1u << (col & 31);
        unsigned old = atomicOr(&g_A[row * NW + (col >> 5)], bit);
        if (!(old & bit)) {
            int pp = atomicAdd(&g_cnt[row], 1);
            if (pp < CAP) g_nbr[row * CAP + pp] = (unsigned short)col;
        }
        float v = 0.69314718055994531f * g_a0[col];
        long long q = __float2ll_rn(v * 4294967296.0f);
        atomicAdd((unsigned long long*)&g_stepq[row], (unsigned long long)q);
    }

    grid_barrier(&g_sync1, gridDim.x);
    hop_body(0, out, vsh, seg, part, blockIdx.x);
    grid_barrier(&g_sync2, gridDim.x);
    hop_body(1, out, vsh, seg, part, blockIdx.x);
}

// ---------------- launch ----------------------------------------------------
extern "C" void kernel_launch(void* const* d_in, const int* in_sizes, int n_in,
                              void* d_out, int out_size) {
    const float* coeffs = (const float*)d_in[0];
    const void*  ei     = d_in[1];
    const float* W0     = (const float*)d_in[2];
    const float* b0     = (const float*)d_in[3];
    const float* W1     = (const float*)d_in[4];
    const float* W2     = (const float*)d_in[5];
    const float* W3     = (const float*)d_in[6];
    const float* b3     = (const float*)d_in[7];
    float* out = (float*)d_out;

    const int ne = in_sizes[1] / 2;

    mlp_mega_kernel<<<257, 128>>>(coeffs, W0, b0, W1, W2, W3, b3, ei);

    mega_kernel<<<MEGA_B, 512>>>(ei, ne, out);
}

// round 15
// speedup vs baseline: 1.0685x; 1.0320x over previous
#include <cuda_runtime.h>
#include <math.h>

#define N      4096
#define D      128
#define NW     128          // 4096 bits / 32
#define MLP_R  16           // rows per MLP block
#define XSTRIDE 36          // dup-x smem row stride (floats)
#define CAP    192          // per-row unique-neighbor list capacity
#define GS     33           // padded stride for a 32-float group in smem
#define MEGA_B 512          // mega kernel blocks (all resident: 148*4=592)
#define HLP_B  128          // helper blocks in kernel 1
#define INV232 2.3283064365386963e-10f   // 2^-32

// ---------------- scratch (device globals) ----------------------------------
__device__ unsigned       g_A  [N * NW];
__device__ unsigned       g_A2 [N * NW];
__device__ unsigned short g_nbr[N * CAP];   // unique neighbor lists
__device__ int            g_cnt[N];
__device__ float          g_Wt [3 * D * D]; // pre-transposed weights, k-major
__device__ float          g_a0[N];
__device__ float          g_av2[N];
__device__ long long      g_stepq[N];
__device__ float          g_step[N];
__device__ int            g_is64;
__device__ unsigned       g_tick[4];        // monotone ticket-barrier counters

#define FMA2(acc, w, x) asm("fma.rn.f32x2 %0, %1, %2, %0;" : "+l"(acc) : "l"(w), "l"(x))
union U64F2 { unsigned long long u; float2 f; };

// ---------------- replay-safe ticket barrier (cohort must be co-resident) ---
__device__ __forceinline__ void ticket_barrier(unsigned* cnt, unsigned cohort) {
    __syncthreads();
    if (threadIdx.x == 0) {
        __threadfence();                              // release (cumulative)
        unsigned t = atomicAdd(cnt, 1u);
        unsigned target = (t / cohort + 1u) * cohort; // my cohort's finish line
        unsigned v;
        do {
            asm volatile("ld.acquire.gpu.global.u32 %0, [%1];"
                         : "=r"(v) : "l"(cnt));
        } while (v < target);
    }
    __syncthreads();
}

// ---------------- kernel 1: MLP blocks (0..255) || helper blocks (256..383) --
// MLP blocks: [0..47 transpose one W tile] -> 256-cohort barrier -> MLP body.
// Helper blocks: zero A/stepq/cnt (+detect) -> 128-cohort barrier ->
//                edge bitset + unique-neighbor-list build (overlaps the MLP).
__global__ __launch_bounds__(128, 4)
void mlp_mega_kernel(const float* __restrict__ coeffs,
                     const float* __restrict__ W0,
                     const float* __restrict__ b0,
                     const float* __restrict__ W1,
                     const float* __restrict__ W2,
                     const float* __restrict__ W3,
                     const float* __restrict__ b3,
                     const void* __restrict__ ei, int ne) {
    __shared__ float xa[128 * XSTRIDE];
    __shared__ float xb[128 * XSTRIDE];

    const int b   = blockIdx.x;
    const int tid = threadIdx.x;

    if (b >= 256) {
        // ================= helper path ======================================
        const int hb  = b - 256;
        const int idx = hb * 128 + tid;            // 0..16383
        const uint4 z = make_uint4(0u, 0u, 0u, 0u);
        uint4* pA = (uint4*)g_A;
        #pragma unroll
        for (int q = 0; q < 8; q++) pA[idx + q * 16384] = z;
        if (idx < 2048) ((uint4*)g_stepq)[idx] = z;
        if (idx < 1024) ((uint4*)g_cnt)[idx]   = z;

        if (hb == 0) {                              // dtype detection
            __shared__ int bad;
            if (tid == 0) bad = 0;
            __syncthreads();
            const long long* p = (const long long*)ei;
            for (int i = tid; i < 2048; i += 128) {
                long long v = p[i];
                if (v < 0 || v >= N) bad = 1;
            }
            __syncthreads();
            if (tid == 0) g_is64 = bad ? 0 : 1;
        }

        ticket_barrier(&g_tick[1], HLP_B);

        // edge bitset + unique neighbor lists (no a0 dependency)
        const int is64 = g_is64;
        for (int e = idx; e < ne; e += HLP_B * 128) {
            int row, col;
            if (is64) {
                const long long* p = (const long long*)ei;
                row = (int)p[e];
                col = (int)p[ne + e];
            } else {
                const int* p = (const int*)ei;
                row = p[e];
                col = p[ne + e];
            }
            unsigned bit = 1u << (col & 31);
            unsigned old = atomicOr(&g_A[row * NW + (col >> 5)], bit);
            if (!(old & bit)) {
                int pp = atomicAdd(&g_cnt[row], 1);
                if (pp < CAP) g_nbr[row * CAP + pp] = (unsigned short)col;
            }
        }
        return;
    }

    // ================= MLP path =============================================
    if (b < 48) {   // transpose one 32x32 tile of W0..W2 into g_Wt (k-major)
        float (*tile)[33] = (float(*)[33])xa;       // alias smem
        const int m = b >> 4;
        const int t = b & 15;
        const int I = t >> 2;                       // c-tile
        const int J = t & 3;                        // k-tile
        const int tx = tid & 31;
        const int ty = tid >> 5;                    // 0..3
        const float* W = (m == 0) ? W0 : (m == 1 ? W1 : W2);
        #pragma unroll
        for (int rr = 0; rr < 8; rr++) {
            int row = ty + rr * 4;
            tile[row][tx] = W[(I * 32 + row) * 128 + J * 32 + tx];
        }
        __syncthreads();
        #pragma unroll
        for (int rr = 0; rr < 8; rr++) {
            int row = ty + rr * 4;
            g_Wt[m * 16384 + (J * 32 + row) * 128 + I * 32 + tx] = tile[tx][row];
        }
    }

    ticket_barrier(&g_tick[0], 256);

    const int r0 = b * MLP_R;
    const int rg = tid >> 4;     // 8 row-groups of 2 rows
    const int cg = tid & 15;     // 16 col-groups

    #pragma unroll
    for (int it = 0; it < 4; it++) {
        int idx = it * 128 + tid;
        int r  = idx >> 5;
        int kq = idx & 31;
        float4 v = *(const float4*)&coeffs[(r0 + r) * 128 + kq * 4];
        float vv[4] = {v.x, v.y, v.z, v.w};
        #pragma unroll
        for (int q = 0; q < 4; q++)
            *(float2*)&xa[(kq * 4 + q) * XSTRIDE + 2 * r] = make_float2(vv[q], vv[q]);
    }
    __syncthreads();

    float* Xin  = xa;
    float* Xout = xb;

    #pragma unroll
    for (int layer = 0; layer < 3; layer++) {
        const float* Wl = g_Wt + layer * 16384;

        unsigned long long a0p[4], a1p[4];
        #pragma unroll
        for (int j = 0; j < 4; j++) { a0p[j] = 0ull; a1p[j] = 0ull; }

        #pragma unroll 8
        for (int k = 0; k < 128; k++) {
            ulonglong2 xx = *(const ulonglong2*)&Xin[k * XSTRIDE + rg * 4];
            const float* wrow = Wl + k * 128 + cg * 2;
            unsigned long long w0 = *(const unsigned long long*)(wrow);
            unsigned long long w1 = *(const unsigned long long*)(wrow + 32);
            unsigned long long w2 = *(const unsigned long long*)(wrow + 64);
            unsigned long long w3 = *(const unsigned long long*)(wrow + 96);
            FMA2(a0p[0], w0, xx.x); FMA2(a1p[0], w0, xx.y);
            FMA2(a0p[1], w1, xx.x); FMA2(a1p[1], w1, xx.y);
            FMA2(a0p[2], w2, xx.x); FMA2(a1p[2], w2, xx.y);
            FMA2(a0p[3], w3, xx.x); FMA2(a1p[3], w3, xx.y);
        }

        float o0[8], o1[8];
        #pragma unroll
        for (int j = 0; j < 4; j++) {
            U64F2 u0, u1; u0.u = a0p[j]; u1.u = a1p[j];
            o0[2 * j] = u0.f.x; o0[2 * j + 1] = u0.f.y;
            o1[2 * j] = u1.f.x; o1[2 * j + 1] = u1.f.y;
        }
        if (layer == 0) {
            #pragma unroll
            for (int j = 0; j < 4; j++) {
                float2 bb = *(const float2*)&b0[32 * j + cg * 2];
                o0[2 * j] += bb.x; o0[2 * j + 1] += bb.y;
                o1[2 * j] += bb.x; o1[2 * j + 1] += bb.y;
            }
        }
        #pragma unroll
        for (int j = 0; j < 8; j++) {
            o0[j] = fmaxf(o0[j], 0.f);
            o1[j] = fmaxf(o1[j], 0.f);
        }

        if (layer < 2) {
            #pragma unroll
            for (int j = 0; j < 4; j++) {
                int k0 = cg * 2 + 32 * j;
                *(float2*)&Xout[(k0    ) * XSTRIDE + 4 * rg    ] = make_float2(o0[2*j],   o0[2*j]);
                *(float2*)&Xout[(k0 + 1) * XSTRIDE + 4 * rg    ] = make_float2(o0[2*j+1], o0[2*j+1]);
                *(float2*)&Xout[(k0    ) * XSTRIDE + 4 * rg + 2] = make_float2(o1[2*j],   o1[2*j]);
                *(float2*)&Xout[(k0 + 1) * XSTRIDE + 4 * rg + 2] = make_float2(o1[2*j+1], o1[2*j+1]);
            }
            __syncthreads();
            float* tmp = Xin; Xin = Xout; Xout = tmp;
        } else {
            float p0 = 0.f, p1 = 0.f;
            #pragma unroll
            for (int j = 0; j < 4; j++) {
                float2 w3v = *(const float2*)&W3[32 * j + cg * 2];
                p0 = fmaf(o0[2*j], w3v.x, fmaf(o0[2*j+1], w3v.y, p0));
                p1 = fmaf(o1[2*j], w3v.x, fmaf(o1[2*j+1], w3v.y, p1));
            }
            #pragma unroll
            for (int off = 8; off; off >>= 1) {
                p0 += __shfl_down_sync(0xffffffffu, p0, off, 16);
                p1 += __shfl_down_sync(0xffffffffu, p1, off, 16);
            }
            if (cg == 0) {
                float bb = b3[0];
                g_a0[r0 + rg * 2]     = p0 + bb;
                g_a0[r0 + rg * 2 + 1] = p1 + bb;
            }
        }
    }
}

// ---------------- hop body (shared by both phases) ----------------------------
__device__ __forceinline__ void hop_body(int phase, float* __restrict__ out_final,
                                         float* vsh, float* seg, float* part,
                                         int blk) {
    const unsigned* M = phase ? g_A2 : g_A;

    const int tid  = threadIdx.x;
    const int wid  = tid >> 5;
    const int lane = tid & 31;
    const int r    = wid >> 1;          // row within block (0..7)
    const int h    = wid & 1;           // column half (0..1)
    const int i    = blk * 8 + r;

    // ---- 1. OR over neighbor rows via unique neighbor list ------------------
    const int woff = h * 64 + 2 * lane;              // this lane's word pair
    const int cnt  = g_cnt[i];
    unsigned ax = 0u, ay = 0u;

    if (cnt <= CAP) {
        const unsigned short* nb = g_nbr + i * CAP;
        int j = 0;
        for (; j + 8 <= cnt; j += 8) {
            uint4 nn = *(const uint4*)&nb[j];        // 8 ushorts, uniform
            int n0 = nn.x & 0xffff, n1 = nn.x >> 16;
            int n2 = nn.y & 0xffff, n3 = nn.y >> 16;
            int n4 = nn.z & 0xffff, n5 = nn.z >> 16;
            int n6 = nn.w & 0xffff, n7 = nn.w >> 16;
            uint2 q0 = __ldg((const uint2*)&M[n0 * NW + woff]);
            uint2 q1 = __ldg((const uint2*)&M[n1 * NW + woff]);
            uint2 q2 = __ldg((const uint2*)&M[n2 * NW + woff]);
            uint2 q3 = __ldg((const uint2*)&M[n3 * NW + woff]);
            uint2 q4 = __ldg((const uint2*)&M[n4 * NW + woff]);
            uint2 q5 = __ldg((const uint2*)&M[n5 * NW + woff]);
            uint2 q6 = __ldg((const uint2*)&M[n6 * NW + woff]);
            uint2 q7 = __ldg((const uint2*)&M[n7 * NW + woff]);
            ax |= ((q0.x | q1.x) | (q2.x | q3.x)) | ((q4.x | q5.x) | (q6.x | q7.x));
            ay |= ((q0.y | q1.y) | (q2.y | q3.y)) | ((q4.y | q5.y) | (q6.y | q7.y));
        }
        for (; j < cnt; j++) {
            int n = nb[j];
            uint2 q = __ldg((const uint2*)&M[n * NW + woff]);
            ax |= q.x; ay |= q.y;
        }
    } else {
        // fallback: bit-walk over the adjacency row (pathological degrees)
        const uint4* Arow = (const uint4*)&g_A[i * NW];
        for (int c = 0; c < 32; c++) {
            uint4 mw = __ldg(&Arow[c]);
            int jb = c * 128;
            unsigned m;
            m = mw.x; while (m) { int b = __ffs((int)m) - 1; m &= m - 1;
                uint2 q = *(const uint2*)&M[(jb + b) * NW + woff]; ax |= q.x; ay |= q.y; }
            m = mw.y; while (m) { int b = __ffs((int)m) - 1; m &= m - 1;
                uint2 q = *(const uint2*)&M[(jb + 32 + b) * NW + woff]; ax |= q.x; ay |= q.y; }
            m = mw.z; while (m) { int b = __ffs((int)m) - 1; m &= m - 1;
                uint2 q = *(const uint2*)&M[(jb + 64 + b) * NW + woff]; ax |= q.x; ay |= q.y; }
            m = mw.w; while (m) { int b = __ffs((int)m) - 1; m &= m - 1;
                uint2 q = *(const uint2*)&M[(jb + 96 + b) * NW + woff]; ax |= q.x; ay |= q.y; }
        }
    }

    if (!phase) *(uint2*)&g_A2[i * NW + woff] = make_uint2(ax, ay);

    // ---- 2. load angle vector, store to padded smem + per-group sums -------
    {
        float vv[8];
        if (phase) {
            float4 u0 = *(const float4*)&g_av2[tid * 8];
            float4 u1 = *(const float4*)&g_av2[tid * 8 + 4];
            vv[0]=u0.x; vv[1]=u0.y; vv[2]=u0.z; vv[3]=u0.w;
            vv[4]=u1.x; vv[5]=u1.y; vv[6]=u1.z; vv[7]=u1.w;
        } else {
            float4 u0 = *(const float4*)&g_a0[tid * 8];
            float4 u1 = *(const float4*)&g_a0[tid * 8 + 4];
            const longlong2* sq = (const longlong2*)g_stepq + tid * 4;
            longlong2 q0 = sq[0], q1 = sq[1], q2 = sq[2], q3 = sq[3];
            vv[0] = u0.x + __ll2float_rn(q0.x) * INV232;
            vv[1] = u0.y + __ll2float_rn(q0.y) * INV232;
            vv[2] = u0.z + __ll2float_rn(q1.x) * INV232;
            vv[3] = u0.w + __ll2float_rn(q1.y) * INV232;
            vv[4] = u1.x + __ll2float_rn(q2.x) * INV232;
            vv[5] = u1.y + __ll2float_rn(q2.y) * INV232;
            vv[6] = u1.z + __ll2float_rn(q3.x) * INV232;
            vv[7] = u1.w + __ll2float_rn(q3.y) * INV232;
        }
        const int g  = tid >> 2;            // 32-float group (one per 4 threads)
        const int o0 = (tid & 3) * 8;       // offset within group
        float s = 0.f;
        #pragma unroll
        for (int q = 0; q < 8; q++) {
            vsh[g * GS + o0 + q] = vv[q];
            s += vv[q];
        }
        s += __shfl_down_sync(0xffffffffu, s, 2, 4);
        s += __shfl_down_sync(0xffffffffu, s, 1, 4);
        if ((tid & 3) == 0) seg[g] = s;
    }
    __syncthreads();

    // ---- 3. gated sum over this lane's two 32-float groups ------------------
    const float* base0 = vsh + woff * GS;          // group woff
    const float* base1 = vsh + (woff + 1) * GS;    // group woff+1
    int pc = __popc(ax) + __popc(ay);
    float sv;
    if (pc > 32) {
        sv = seg[woff] + seg[woff + 1];
        unsigned m;
        m = ~ax; while (m) { int b = __ffs((int)m) - 1; m &= m - 1; sv -= base0[b]; }
        m = ~ay; while (m) { int b = __ffs((int)m) - 1; m &= m - 1; sv -= base1[b]; }
    } else {
        sv = 0.f;
        unsigned m;
        m = ax; while (m) { int b = __ffs((int)m) - 1; m &= m - 1; sv += base0[b]; }
        m = ay; while (m) { int b = __ffs((int)m) - 1; m &= m - 1; sv += base1[b]; }
    }
    #pragma unroll
    for (int o = 16; o; o >>= 1) sv += __shfl_down_sync(0xffffffffu, sv, o);
    if (lane == 0) part[wid] = sv;
    __syncthreads();

    // ---- 4. combine halves + epilogue (threads 0..7 handle rows 0..7) ------
    if (tid < 8) {
        const int ii = blk * 8 + tid;
        float vi = vsh[(ii >> 5) * GS + (ii & 31)];
        float tot = part[2 * tid] + part[2 * tid + 1];
        if (!phase) {
            float s1 = __ll2float_rn(g_stepq[ii]) * INV232;
            float ns = s1 + 1.0986122886681098f * tot;            // ln 3
            g_step[ii] = ns;
            g_av2[ii]  = vi + ns;                                  // a1 + step
        } else {
            out_final[ii] = vi + g_step[ii] + 1.3862943611198906f * tot; // ln 4
        }
    }
}

// ---------------- mega: stepq scatter + barrier + hop0 + barrier + hop1 ------
__global__ __launch_bounds__(512, 4)
void mega_kernel(const void* __restrict__ ei, int ne, float* __restrict__ out) {
    __shared__ float vsh[128 * GS];
    __shared__ float seg[128];
    __shared__ float part[16];

    // ---- hop-1 scatter only (bitset + nbr lists built in kernel 1) ---------
    const int is64   = g_is64;
    const int stride = gridDim.x * blockDim.x;
    for (int e = blockIdx.x * blockDim.x + threadIdx.x; e < ne; e += stride) {
        int row, col;
        if (is64) {
            const long long* p = (const long long*)ei;
            row = (int)p[e];
            col = (int)p[ne + e];
        } else {
            const int* p = (const int*)ei;
            row = p[e];
            col = p[ne + e];
        }
        float v = 0.69314718055994531f * g_a0[col];
        long long q = __float2ll_rn(v * 4294967296.0f);
        atomicAdd((unsigned long long*)&g_stepq[row], (unsigned long long)q);
    }

    ticket_barrier(&g_tick[2], MEGA_B);
    hop_body(0, out, vsh, seg, part, blockIdx.x);
    ticket_barrier(&g_tick[3], MEGA_B);
    hop_body(1, out, vsh, seg, part, blockIdx.x);
}

// ---------------- launch ----------------------------------------------------
extern "C" void kernel_launch(void* const* d_in, const int* in_sizes, int n_in,
                              void* d_out, int out_size) {
    const float* coeffs = (const float*)d_in[0];
    const void*  ei     = d_in[1];
    const float* W0     = (const float*)d_in[2];
    const float* b0     = (const float*)d_in[3];
    const float* W1     = (const float*)d_in[4];
    const float* W2     = (const float*)d_in[5];
    const float* W3     = (const float*)d_in[6];
    const float* b3     = (const float*)d_in[7];
    float* out = (float*)d_out;

    const int ne = in_sizes[1] / 2;

    mlp_mega_kernel<<<256 + HLP_B, 128>>>(coeffs, W0, b0, W1, W2, W3, b3, ei, ne);

    mega_kernel<<<MEGA_B, 512>>>(ei, ne, out);
}